// round 1
// baseline (speedup 1.0000x reference)
#include <cuda_runtime.h>
#include <cuda_bf16.h>
#include <cstdint>
#include <math.h>

// ---------------------------------------------------------------------------
// SimpleModelQ: attention-pooling + MLP, algebraically collapsed.
//
//   score[b,s] = (M @ archi[b] + c) . feats[b,s] / sqrt(258)   (+const, cancels)
//   fbar[b]    = sum_s softmax(score)[s] * feats[b,s]          (255-dim)
//   res        = vW @ fbar + vb
//   h1 = relu(res @ W1^T + b1); h2 = relu(h1 @ W2^T + b2); out = h2 @ W3^T + b3
// ---------------------------------------------------------------------------

#define B_     128
#define S_     1024
#define LAST_  258
#define FEAT_  255
#define HID_   1024

// ---- device scratch (zero-initialized at module load; fully rewritten each call
//      except padding rows which must stay zero) ----
__device__ float g_qkp[256 * 4];        // [f][{M0,M1,M2,c}], row 255 unused
__device__ float g_fbarT[256 * 128];    // k-major [f][b]; row 255 stays 0 (pad)
__device__ float g_resT[1024 * 128];    // [h][b]
__device__ float g_h1T[512 * 128];
__device__ float g_h2T[256 * 128];
__device__ float g_P[4096 * 128];       // split-K partials (max 8 splits x 512 n)

// ===========================================================================
// K0: M[f][j] = sum_h qW[h,j]*kW[h,f];  c[f] = sum_h qb[h]*kW[h,f]
// grid 255 blocks (one per f), 128 threads
// ===========================================================================
__global__ void k0_kernel(const float* __restrict__ kW,
                          const float* __restrict__ qW,
                          const float* __restrict__ qb) {
    int f = blockIdx.x;
    int t = threadIdx.x;
    int lane = t & 31, w = t >> 5;
    float m0 = 0.f, m1 = 0.f, m2 = 0.f, cc = 0.f;
#pragma unroll
    for (int j = 0; j < 8; j++) {
        int h = t + j * 128;
        float kv = kW[(size_t)h * FEAT_ + f];
        m0 += kv * qW[h * 3 + 0];
        m1 += kv * qW[h * 3 + 1];
        m2 += kv * qW[h * 3 + 2];
        cc += kv * qb[h];
    }
#pragma unroll
    for (int off = 16; off; off >>= 1) {
        m0 += __shfl_xor_sync(0xffffffffu, m0, off);
        m1 += __shfl_xor_sync(0xffffffffu, m1, off);
        m2 += __shfl_xor_sync(0xffffffffu, m2, off);
        cc += __shfl_xor_sync(0xffffffffu, cc, off);
    }
    __shared__ float red[4][4];
    if (lane == 0) { red[w][0] = m0; red[w][1] = m1; red[w][2] = m2; red[w][3] = cc; }
    __syncthreads();
    if (t == 0) {
        float r0 = red[0][0] + red[1][0] + red[2][0] + red[3][0];
        float r1 = red[0][1] + red[1][1] + red[2][1] + red[3][1];
        float r2 = red[0][2] + red[1][2] + red[2][2] + red[3][2];
        float r3 = red[0][3] + red[1][3] + red[2][3] + red[3][3];
        g_qkp[f * 4 + 0] = r0;
        g_qkp[f * 4 + 1] = r1;
        g_qkp[f * 4 + 2] = r2;
        g_qkp[f * 4 + 3] = r3;
    }
}

// ===========================================================================
// K1: single-pass attention pooling (flash-style online softmax).
// One CTA per batch, 1024 threads, 16 chunks of 64 rows staged via cp.async.
// ===========================================================================
#define CHUNK_  64
#define ROWF_   256
#define NCH_    16

// shared memory layout (in floats)
#define K1_BUF   0                         // 2 * 64 * 256 = 32768
#define K1_QK    32768                     // 256
#define K1_SC    (K1_QK + 256)             // 64
#define K1_PV    (K1_SC + 64)              // 64
#define K1_RED   (K1_PV + 64)              // 8
#define K1_ST    (K1_RED + 8)              // 8   (0:m  1:l  2:alpha)
#define K1_FRED  (K1_ST + 8)               // 1024
#define K1_TOTF  (K1_FRED + 1024)
#define K1_SMEM_BYTES (K1_TOTF * 4)

__device__ __forceinline__ void cp_async8(uint32_t saddr, const void* gaddr) {
    asm volatile("cp.async.ca.shared.global [%0], [%1], 8;" :: "r"(saddr), "l"(gaddr));
}

__global__ void __launch_bounds__(1024, 1)
attn_kernel(const float* __restrict__ input) {
    extern __shared__ float sm[];
    const int b   = blockIdx.x;
    const int tid = threadIdx.x;
    const int lane = tid & 31;
    const int w    = tid >> 5;
    const uint32_t smem_u32 = (uint32_t)__cvta_generic_to_shared(sm);

    const float* gbase = input + (size_t)b * S_ * LAST_;

    // --- issue first chunk load immediately ---
    {
        const float* gsrc = gbase;
        uint32_t sb = smem_u32 + (uint32_t)(K1_BUF * 4);
#pragma unroll
        for (int j = 0; j < 8; j++) {
            int idx = tid + j * 1024;
            int r = idx >> 7, c2 = idx & 127;
            cp_async8(sb + (uint32_t)((r * ROWF_ + c2 * 2) * 4), gsrc + r * LAST_ + c2 * 2);
        }
        asm volatile("cp.async.commit_group;");
    }

    // --- prologue: per-batch qk vector from precomputed params ---
    const float a0 = gbase[FEAT_ + 0];
    const float a1 = gbase[FEAT_ + 1];
    const float a2 = gbase[FEAT_ + 2];
    const float scale = rsqrtf(258.0f);
    if (tid < 256) {
        float4 pr = ((const float4*)g_qkp)[tid];
        float v = (tid < FEAT_) ? (pr.x * a0 + pr.y * a1 + pr.z * a2 + pr.w) * scale : 0.f;
        sm[K1_QK + tid] = v;
    }
    if (tid == 0) { sm[K1_ST + 0] = -INFINITY; sm[K1_ST + 1] = 0.f; }
    __syncthreads();

    // per-lane qk register cache (8 floats): elements [lane*8, lane*8+8)
    const float4* qk4 = (const float4*)(sm + K1_QK);
    const float4 qA = qk4[lane * 2];
    const float4 qB = qk4[lane * 2 + 1];

    const int col = tid & 255;
    const int grp = tid >> 8;          // 4 groups of 16 rows each
    float acc = 0.f;

    for (int c = 0; c < NCH_; c++) {
        // prefetch next chunk into other buffer half
        if (c + 1 < NCH_) {
            const float* gsrc = gbase + (size_t)(c + 1) * CHUNK_ * LAST_;
            uint32_t sb = smem_u32 + (uint32_t)((K1_BUF + ((c + 1) & 1) * CHUNK_ * ROWF_) * 4);
#pragma unroll
            for (int j = 0; j < 8; j++) {
                int idx = tid + j * 1024;
                int r = idx >> 7, c2 = idx & 127;
                cp_async8(sb + (uint32_t)((r * ROWF_ + c2 * 2) * 4), gsrc + r * LAST_ + c2 * 2);
            }
            asm volatile("cp.async.commit_group;");
            asm volatile("cp.async.wait_group 1;");
        } else {
            asm volatile("cp.async.wait_group 0;");
        }
        __syncthreads();

        const float* cur = sm + K1_BUF + (c & 1) * CHUNK_ * ROWF_;

        // ---- scores: warp w handles rows 2w, 2w+1 ----
        {
            int r0 = 2 * w, r1 = r0 + 1;
            const float4* rp0 = (const float4*)(cur + r0 * ROWF_);
            const float4* rp1 = (const float4*)(cur + r1 * ROWF_);
            float4 x0 = rp0[lane * 2], x1 = rp0[lane * 2 + 1];
            float4 y0 = rp1[lane * 2], y1 = rp1[lane * 2 + 1];
            float v0 = x0.x * qA.x + x0.y * qA.y + x0.z * qA.z + x0.w * qA.w
                     + x1.x * qB.x + x1.y * qB.y + x1.z * qB.z + x1.w * qB.w;
            float v1 = y0.x * qA.x + y0.y * qA.y + y0.z * qA.z + y0.w * qA.w
                     + y1.x * qB.x + y1.y * qB.y + y1.z * qB.z + y1.w * qB.w;
#pragma unroll
            for (int off = 16; off; off >>= 1) {
                v0 += __shfl_xor_sync(0xffffffffu, v0, off);
                v1 += __shfl_xor_sync(0xffffffffu, v1, off);
            }
            if (lane == 0) { sm[K1_SC + r0] = v0; sm[K1_SC + r1] = v1; }
        }
        __syncthreads();

        // ---- online softmax bookkeeping ----
        if (tid < 64) {
            float sc = sm[K1_SC + tid];
            float mx = sc;
#pragma unroll
            for (int off = 16; off; off >>= 1)
                mx = fmaxf(mx, __shfl_xor_sync(0xffffffffu, mx, off));
            if ((tid & 31) == 0) sm[K1_RED + (tid >> 5)] = mx;
        }
        __syncthreads();
        if (tid == 0) {
            float chm  = fmaxf(sm[K1_RED + 0], sm[K1_RED + 1]);
            float mold = sm[K1_ST + 0];
            float mnew = fmaxf(mold, chm);
            sm[K1_ST + 2] = __expf(mold - mnew);
            sm[K1_ST + 0] = mnew;
        }
        __syncthreads();
        float mnew  = sm[K1_ST + 0];
        float alpha = sm[K1_ST + 2];
        if (tid < 64) {
            float p = __expf(sm[K1_SC + tid] - mnew);
            sm[K1_PV + tid] = p;
            float ps = p;
#pragma unroll
            for (int off = 16; off; off >>= 1)
                ps += __shfl_xor_sync(0xffffffffu, ps, off);
            if ((tid & 31) == 0) sm[K1_RED + 2 + (tid >> 5)] = ps;
        }
        __syncthreads();
        if (tid == 0)
            sm[K1_ST + 1] = sm[K1_ST + 1] * alpha + sm[K1_RED + 2] + sm[K1_RED + 3];

        // ---- fbar accumulation: thread owns (grp rows [grp*16,grp*16+16), col) ----
        acc *= alpha;
#pragma unroll
        for (int j = 0; j < 16; j++) {
            int r = grp * 16 + j;
            acc += sm[K1_PV + r] * cur[r * ROWF_ + col];
        }
        __syncthreads();   // protect buf half + score/pv arrays for next chunk
    }

    // ---- epilogue: reduce 4 group partials, normalize, write fbar^T ----
    sm[K1_FRED + grp * 256 + col] = acc;
    __syncthreads();
    if (tid < FEAT_) {
        float s = sm[K1_FRED + tid] + sm[K1_FRED + 256 + tid]
                + sm[K1_FRED + 512 + tid] + sm[K1_FRED + 768 + tid];
        g_fbarT[tid * 128 + b] = s / sm[K1_ST + 1];
    }
}

// ===========================================================================
// Generic split-K partial GEMM:  P[ky][n][b] = sum_{k in chunk} AT[k][b]*W[n][k]
// AT is k-major (rows padded with zeros beyond K). Tile: 32 n x 128 b.
// block 256 threads: (b = tid&127, half = tid>>7), 16 outputs each.
// ===========================================================================
__global__ void __launch_bounds__(256)
gemm_partial(const float* __restrict__ AT, const float* __restrict__ W,
             float* __restrict__ P, int K, int N, int KCH) {
    __shared__ float Wt[32 * 32];   // [kk][nn]
    const int tid  = threadIdx.x;
    const int b    = tid & 127;
    const int half = tid >> 7;
    const int n0   = blockIdx.x * 32;
    const int kbase = blockIdx.y * KCH;
    const int kend  = min(K, kbase + KCH);

    float acc[16];
#pragma unroll
    for (int i = 0; i < 16; i++) acc[i] = 0.f;

    for (int k0 = kbase; k0 < kend; k0 += 32) {
#pragma unroll
        for (int j = 0; j < 4; j++) {
            int e  = tid + j * 256;
            int nn = e >> 5, kk = e & 31;
            int k = k0 + kk, n = n0 + nn;
            Wt[kk * 32 + nn] = (k < kend && n < N) ? W[(size_t)n * K + k] : 0.f;
        }
        __syncthreads();
#pragma unroll
        for (int kk = 0; kk < 32; kk++) {
            float a = AT[(size_t)(k0 + kk) * 128 + b];  // pad rows beyond K are zero
            const float4* wr = (const float4*)&Wt[kk * 32 + half * 16];
            float4 w0 = wr[0], w1 = wr[1], w2 = wr[2], w3 = wr[3];
            acc[0]  += a * w0.x; acc[1]  += a * w0.y; acc[2]  += a * w0.z; acc[3]  += a * w0.w;
            acc[4]  += a * w1.x; acc[5]  += a * w1.y; acc[6]  += a * w1.z; acc[7]  += a * w1.w;
            acc[8]  += a * w2.x; acc[9]  += a * w2.y; acc[10] += a * w2.z; acc[11] += a * w2.w;
            acc[12] += a * w3.x; acc[13] += a * w3.y; acc[14] += a * w3.z; acc[15] += a * w3.w;
        }
        __syncthreads();
    }
#pragma unroll
    for (int i = 0; i < 16; i++) {
        int n = n0 + half * 16 + i;
        if (n < N) P[((size_t)blockIdx.y * N + n) * 128 + b] = acc[i];
    }
}

// ===========================================================================
// Reduce split-K partials + bias (+optional relu), write k-major output.
// grid N, block 128 (one thread per batch).
// ===========================================================================
__global__ void reduce_bias(const float* __restrict__ P, const float* __restrict__ bias,
                            float* __restrict__ outT, int N, int KS, int relu) {
    int n = blockIdx.x, b = threadIdx.x;
    float s = bias[n];
    for (int ks = 0; ks < KS; ks++) s += P[((size_t)ks * N + n) * 128 + b];
    if (relu) s = fmaxf(s, 0.f);
    outT[(size_t)n * 128 + b] = s;
}

// ===========================================================================
// Final layer: out[b][j] = h2[b] . W3[j] + b3[j]   (N=2, K=256). One CTA.
// ===========================================================================
__global__ void __launch_bounds__(512)
final_kernel(const float* __restrict__ h2T, const float* __restrict__ W3,
             const float* __restrict__ b3, float* __restrict__ out) {
    __shared__ float w3s[512];
    __shared__ float r0[4][128], r1[4][128];
    int tid = threadIdx.x;
    if (tid < 512) w3s[tid] = W3[tid];
    __syncthreads();
    int b = tid & 127, g = tid >> 7;
    float a0 = 0.f, a1 = 0.f;
#pragma unroll 8
    for (int j = 0; j < 64; j++) {
        int k = g * 64 + j;
        float a = h2T[(size_t)k * 128 + b];
        a0 += a * w3s[k];
        a1 += a * w3s[256 + k];
    }
    r0[g][b] = a0; r1[g][b] = a1;
    __syncthreads();
    if (tid < 128) {
        out[b * 2 + 0] = r0[0][b] + r0[1][b] + r0[2][b] + r0[3][b] + b3[0];
        out[b * 2 + 1] = r1[0][b] + r1[1][b] + r1[2][b] + r1[3][b] + b3[1];
    }
}

// ===========================================================================
extern "C" void kernel_launch(void* const* d_in, const int* in_sizes, int n_in,
                              void* d_out, int out_size) {
    const float* input = (const float*)d_in[0];
    const float* kW = (const float*)d_in[1];
    // kb (d_in[2]) only shifts scores by a per-batch constant -> cancels in softmax
    const float* vW = (const float*)d_in[3];
    const float* vb = (const float*)d_in[4];
    const float* qW = (const float*)d_in[5];
    const float* qb = (const float*)d_in[6];
    const float* W1 = (const float*)d_in[7];
    const float* b1 = (const float*)d_in[8];
    const float* W2 = (const float*)d_in[9];
    const float* b2 = (const float*)d_in[10];
    const float* W3 = (const float*)d_in[11];
    const float* b3 = (const float*)d_in[12];
    float* out = (float*)d_out;

    cudaFuncSetAttribute(attn_kernel, cudaFuncAttributeMaxDynamicSharedMemorySize,
                         K1_SMEM_BYTES);

    void *p_fbar, *p_res, *p_h1, *p_h2, *p_P;
    cudaGetSymbolAddress(&p_fbar, g_fbarT);
    cudaGetSymbolAddress(&p_res,  g_resT);
    cudaGetSymbolAddress(&p_h1,   g_h1T);
    cudaGetSymbolAddress(&p_h2,   g_h2T);
    cudaGetSymbolAddress(&p_P,    g_P);

    // K0: qk-projection params (input-independent per launch)
    k0_kernel<<<255, 128>>>(kW, qW, qb);

    // K1: attention pooling -> g_fbarT (255 x 128, row 255 = zero pad)
    attn_kernel<<<128, 1024, K1_SMEM_BYTES>>>(input);

    // res = vW @ fbar + vb        (N=1024, K=255)
    gemm_partial<<<dim3(32, 2), 256>>>((const float*)p_fbar, vW, (float*)p_P, 255, 1024, 128);
    reduce_bias<<<1024, 128>>>((const float*)p_P, vb, (float*)p_res, 1024, 2, 0);

    // h1 = relu(res @ W1^T + b1)  (N=512, K=1024)
    gemm_partial<<<dim3(16, 8), 256>>>((const float*)p_res, W1, (float*)p_P, 1024, 512, 128);
    reduce_bias<<<512, 128>>>((const float*)p_P, b1, (float*)p_h1, 512, 8, 1);

    // h2 = relu(h1 @ W2^T + b2)   (N=256, K=512)
    gemm_partial<<<dim3(8, 4), 256>>>((const float*)p_h1, W2, (float*)p_P, 512, 256, 128);
    reduce_bias<<<256, 128>>>((const float*)p_P, b2, (float*)p_h2, 256, 4, 1);

    // out = h2 @ W3^T + b3        (N=2, K=256)
    final_kernel<<<1, 512>>>((const float*)p_h2, W3, b3, out);
}